// round 3
// baseline (speedup 1.0000x reference)
#include <cuda_runtime.h>
#include <math.h>

#define T_ 64
#define M_ 256
#define K_ 6
#define B_ 256
#define H_ 256
#define L_ 128
#define V_ 780
#define E_ 16384
#define DC_ 383          // wcls cols = H+L-1
#define DS_ 638          // ucls cols = 2H+L-2
#define NROWS (E_ + B_)  // msg rows + root rows

// ------------------------- device scratch (static, no runtime alloc) -----
__device__ float  g_hbuf [(E_ + 1) * H_];     // hbuf rows (row E_ = PAD = e0)
__device__ float  g_h1buf[(E_ + 1) * H_];     // _llinear(hbuf, W0, b0, s0) per row
__device__ float  g_W1T  [512 * H_];          // W1^T padded to 512 rows
__device__ float  g_W0T  [H_ * H_];           // W0^T
__device__ float  g_Gt   [384 * V_];          // centroid matrix (i-major), row 0 = -wcls[:,0], row 383 = 0
__device__ float  g_X    [NROWS * 384];       // concat vectors for centroid GEMM (padded to 384)
__device__ float  g_scores[NROWS * V_];       // pred scores
__device__ double g_acc[6];                   // 0:pred_loss 1:pred_hit 2:pmask 3:stop_loss 4:stop_hit

// ------------------------- helpers ---------------------------------------
__device__ __forceinline__ float blockReduceSum(float v, float* sh) {
    __syncthreads();
    #pragma unroll
    for (int o = 16; o > 0; o >>= 1) v += __shfl_down_sync(0xffffffffu, v, o);
    int tid = threadIdx.x;
    if ((tid & 31) == 0) sh[tid >> 5] = v;
    __syncthreads();
    if (tid < 32) {
        int nw = (blockDim.x + 31) >> 5;
        v = (tid < nw) ? sh[tid] : 0.f;
        #pragma unroll
        for (int o = 16; o > 0; o >>= 1) v += __shfl_down_sync(0xffffffffu, v, o);
        if (tid == 0) sh[0] = v;
    }
    __syncthreads();
    return sh[0];
}

// ------------------------- prep: transposes + Gt + accumulator zero ------
__global__ void prep_misc(const float* __restrict__ W0,
                          const float* __restrict__ W1,
                          const float* __restrict__ wcls) {
    const int n1 = 512 * H_;       // W1T
    const int n2 = H_ * H_;        // W0T
    const int n3 = 384 * V_;       // Gt
    for (int idx = blockIdx.x * blockDim.x + threadIdx.x;
         idx < n1 + n2 + n3; idx += gridDim.x * blockDim.x) {
        if (idx < n1) {
            int i = idx >> 8, j = idx & 255;
            g_W1T[idx] = (i < 511) ? W1[j * 511 + i] : 0.f;
        } else if (idx < n1 + n2) {
            int k = idx - n1;
            int i = k >> 8, j = k & 255;
            g_W0T[k] = W0[j * H_ + i];
        } else {
            int k = idx - n1 - n2;
            int i = k / V_, v = k % V_;
            float g;
            if (i == 0)      g = -wcls[v * DC_];
            else if (i < DC_) g = wcls[v * DC_ + i];
            else              g = 0.f;
            g_Gt[k] = g;
        }
    }
}

// pad row (row E_): hbuf = e0, h1buf = llinear(e0 @ W0^T + b0); zero accumulators
__global__ void prep_pad(const float* __restrict__ W0,
                         const float* __restrict__ b0,
                         const float* __restrict__ s0p) {
    __shared__ float red[32];
    __shared__ float ybc;
    int tid = threadIdx.x;
    if (tid < 6) g_acc[tid] = 0.0;
    g_hbuf[E_ * H_ + tid] = (tid == 0) ? 1.f : 0.f;
    // e0 @ W0^T -> column 0 of W0 rows
    float y = W0[tid * H_] + b0[tid];
    if (tid == 0) ybc = y;
    float ss = blockReduceSum((tid == 0) ? 0.f : y * y, red);
    float time = expf(s0p[0]) / (1.f + expf(-ybc)) + 1.1f;
    float sc = sqrtf((time * time - 1.f) / fmaxf(ss, 1e-8f));
    g_h1buf[E_ * H_ + tid] = (tid == 0) ? time : y * sc;
}

// ------------------------- scan step (4 rows / block, 64 blocks) ---------
__global__ void step_kernel(int t,
                            const int*   __restrict__ wid,
                            const int*   __restrict__ nhi,
                            const float* __restrict__ nhw,
                            const float* __restrict__ emb,
                            const float* __restrict__ b0,
                            const float* __restrict__ s0p,
                            const float* __restrict__ b1,
                            const float* __restrict__ s1p) {
    __shared__ float svec[4][512];   // concat(cur_x, h1m)  (511 + pad)
    __shared__ float shv [4][256];   // new_h rows
    __shared__ float red[32];
    __shared__ float ybc;
    int tid = threadIdx.x;
    float e_s0 = expf(s0p[0]);
    float e_s1 = expf(s1p[0]);

    // phase 1: gathered midpoint over h1buf, build concat vectors
    for (int r = 0; r < 4; r++) {
        int e = t * M_ + blockIdx.x * 4 + r;
        float wsum = 0.f, a = 0.f;
        #pragma unroll
        for (int k = 0; k < K_; k++) {
            int   id = nhi[e * K_ + k];
            float w  = nhw[e * K_ + k];
            wsum += w;
            a += w * g_h1buf[id * H_ + tid];
        }
        a /= fmaxf(wsum, 1e-8f);
        float inner = blockReduceSum((tid == 0) ? -a * a : a * a, red);
        float h1m = a / sqrtf(fmaxf(-inner, 1e-8f));
        float cx = emb[wid[e] * H_ + tid];
        if (tid == 0) {
            svec[r][0]   = sqrtf(fmaxf(cx * cx + h1m * h1m - 1.0f, 1e-8f));
            svec[r][511] = 0.f;
        } else {
            svec[r][tid]       = cx;
            svec[r][255 + tid] = h1m;
        }
    }
    __syncthreads();

    // phase 2: GEMM with W1^T (511 padded to 512)
    float acc0 = b1[tid], acc1 = acc0, acc2 = acc0, acc3 = acc0;
    {
        const float4* s0v = (const float4*)svec[0];
        const float4* s1v = (const float4*)svec[1];
        const float4* s2v = (const float4*)svec[2];
        const float4* s3v = (const float4*)svec[3];
        #pragma unroll 4
        for (int i4 = 0; i4 < 128; i4++) {
            int base = (i4 * 4) * H_ + tid;
            float w0 = g_W1T[base], w1 = g_W1T[base + H_];
            float w2 = g_W1T[base + 2 * H_], w3 = g_W1T[base + 3 * H_];
            float4 x0 = s0v[i4], x1 = s1v[i4], x2 = s2v[i4], x3 = s3v[i4];
            acc0 += w0 * x0.x + w1 * x0.y + w2 * x0.z + w3 * x0.w;
            acc1 += w0 * x1.x + w1 * x1.y + w2 * x1.z + w3 * x1.w;
            acc2 += w0 * x2.x + w1 * x2.y + w2 * x2.z + w3 * x2.w;
            acc3 += w0 * x3.x + w1 * x3.y + w2 * x3.z + w3 * x3.w;
        }
    }
    float accs[4] = {acc0, acc1, acc2, acc3};
    for (int r = 0; r < 4; r++) {
        __syncthreads();
        float y = accs[r];
        if (tid == 0) ybc = y;
        float ss = blockReduceSum((tid == 0) ? 0.f : y * y, red);
        float time = e_s1 / (1.f + expf(-ybc)) + 1.1f;
        float sc = sqrtf((time * time - 1.f) / fmaxf(ss, 1e-8f));
        float outv = (tid == 0) ? time : y * sc;
        int e = t * M_ + blockIdx.x * 4 + r;
        g_hbuf[e * H_ + tid] = outv;
        shv[r][tid] = outv;
    }
    __syncthreads();

    // phase 3: GEMM with W0^T, produce h1buf rows
    float c0 = b0[tid], c1 = c0, c2 = c0, c3 = c0;
    {
        const float4* s0v = (const float4*)shv[0];
        const float4* s1v = (const float4*)shv[1];
        const float4* s2v = (const float4*)shv[2];
        const float4* s3v = (const float4*)shv[3];
        #pragma unroll 4
        for (int i4 = 0; i4 < 64; i4++) {
            int base = (i4 * 4) * H_ + tid;
            float w0 = g_W0T[base], w1 = g_W0T[base + H_];
            float w2 = g_W0T[base + 2 * H_], w3 = g_W0T[base + 3 * H_];
            float4 x0 = s0v[i4], x1 = s1v[i4], x2 = s2v[i4], x3 = s3v[i4];
            c0 += w0 * x0.x + w1 * x0.y + w2 * x0.z + w3 * x0.w;
            c1 += w0 * x1.x + w1 * x1.y + w2 * x1.z + w3 * x1.w;
            c2 += w0 * x2.x + w1 * x2.y + w2 * x2.z + w3 * x2.w;
            c3 += w0 * x3.x + w1 * x3.y + w2 * x3.z + w3 * x3.w;
        }
    }
    float accs2[4] = {c0, c1, c2, c3};
    for (int r = 0; r < 4; r++) {
        __syncthreads();
        float y = accs2[r];
        if (tid == 0) ybc = y;
        float ss = blockReduceSum((tid == 0) ? 0.f : y * y, red);
        float time = e_s0 / (1.f + expf(-ybc)) + 1.1f;
        float sc = sqrtf((time * time - 1.f) / fmaxf(ss, 1e-8f));
        int e = t * M_ + blockIdx.x * 4 + r;
        g_h1buf[e * H_ + tid] = (tid == 0) ? time : y * sc;
    }
}

// ------------------------- build X rows for centroid GEMM ----------------
__global__ void xbuild(const int* __restrict__ bidx, const float* __restrict__ xtv) {
    int row = blockIdx.x, tid = threadIdx.x;  // 384 threads
    float v = 0.f;
    if (row < E_) {
        const float* ctx = xtv + bidx[row] * L_;
        if (tid == 0) {
            float n0 = g_hbuf[row * H_];
            float c0 = ctx[0];
            v = sqrtf(fmaxf(n0 * n0 + c0 * c0 - 1.f, 1e-8f));
        } else if (tid < H_) v = g_hbuf[row * H_ + tid];
        else if (tid < DC_)  v = ctx[tid - 255];
    } else {
        const float* ctx = xtv + (row - E_) * L_;
        if (tid == 0) v = sqrtf(fmaxf(ctx[0] * ctx[0], 1e-8f));  // concat(origin, xtv)
        else if (tid >= H_ && tid < DC_) v = ctx[tid - 255];
        // spatial part of origin is zero
    }
    g_X[row * 384 + tid] = v;
}

// ------------------------- centroid scores GEMM (16 rows / block) --------
__global__ void scores_kernel(const float* __restrict__ wbias) {
    __shared__ float xs[16][384];
    int rb = blockIdx.x * 16, tid = threadIdx.x;
    float* xf = (float*)xs;
    for (int idx = tid; idx < 16 * 384; idx += 256) xf[idx] = g_X[rb * 384 + idx];
    __syncthreads();
    for (int cc = 0; cc < 4; cc++) {
        int col = cc * 256 + tid;
        if (col < V_) {
            float acc[16];
            #pragma unroll
            for (int r = 0; r < 16; r++) acc[r] = 0.f;
            for (int i = 0; i < 384; i += 4) {
                float g0 = g_Gt[(i + 0) * V_ + col];
                float g1 = g_Gt[(i + 1) * V_ + col];
                float g2 = g_Gt[(i + 2) * V_ + col];
                float g3 = g_Gt[(i + 3) * V_ + col];
                #pragma unroll
                for (int r = 0; r < 16; r++) {
                    float4 xv = *(const float4*)&xs[r][i];
                    acc[r] += g0 * xv.x + g1 * xv.y + g2 * xv.z + g3 * xv.w;
                }
            }
            float bb = wbias[col];
            #pragma unroll
            for (int r = 0; r < 16; r++)
                g_scores[(rb + r) * V_ + col] = 2.f + 2.f * acc[r] + bb;
        }
    }
}

// ------------------------- CE + argmax over V for pred head --------------
__global__ void ce_kernel(const int* __restrict__ dir,
                          const int* __restrict__ ptg,
                          const int* __restrict__ rwid) {
    int row = blockIdx.x, tid = threadIdx.x;
    __shared__ float red[32];
    __shared__ float smax[8];
    __shared__ int   simax[8];
    __shared__ float gmv;
    __shared__ int   gmi;
    const float* s = g_scores + row * V_;
    float mx = -1e30f; int mi = 0x7fffffff;
    for (int j = tid; j < V_; j += 256) {
        float v = s[j];
        if (v > mx) { mx = v; mi = j; }
    }
    #pragma unroll
    for (int o = 16; o > 0; o >>= 1) {
        float ov = __shfl_down_sync(0xffffffffu, mx, o);
        int   oi = __shfl_down_sync(0xffffffffu, mi, o);
        if (ov > mx || (ov == mx && oi < mi)) { mx = ov; mi = oi; }
    }
    if ((tid & 31) == 0) { smax[tid >> 5] = mx; simax[tid >> 5] = mi; }
    __syncthreads();
    if (tid == 0) {
        for (int w = 1; w < 8; w++) {
            if (smax[w] > mx || (smax[w] == mx && simax[w] < mi)) { mx = smax[w]; mi = simax[w]; }
        }
        gmv = mx; gmi = mi;
    }
    __syncthreads();
    float m = gmv;
    float p = 0.f;
    for (int j = tid; j < V_; j += 256) p += expf(s[j] - m);
    float sum = blockReduceSum(p, red);
    if (tid == 0) {
        float lse = m + logf(sum);
        if (row < E_) {
            float pm = (float)dir[row];
            int tgt = ptg[row];
            float ce = lse - s[tgt];
            atomicAdd(&g_acc[0], (double)(pm * ce));
            atomicAdd(&g_acc[1], (double)(pm * ((gmi == tgt) ? 1.f : 0.f)));
            atomicAdd(&g_acc[2], (double)pm);
        } else {
            int tgt = rwid[row - E_];
            float ce = lse - s[tgt];
            atomicAdd(&g_acc[0], (double)ce);
            atomicAdd(&g_acc[1], (gmi == tgt) ? 1.0 : 0.0);
        }
    }
}

// ------------------------- stop head (fused build + score + CE) ----------
__global__ void stop_kernel(const int*   __restrict__ wid,
                            const int*   __restrict__ noi,
                            const float* __restrict__ now,
                            const int*   __restrict__ bidx,
                            const int*   __restrict__ dir,
                            const int*   __restrict__ rwid,
                            const int*   __restrict__ roi,
                            const float* __restrict__ row_w,
                            const float* __restrict__ xtv,
                            const float* __restrict__ emb,
                            const float* __restrict__ ucls,
                            const float* __restrict__ ubias) {
    int row = blockIdx.x, tid = threadIdx.x;
    __shared__ float red[32];
    int widx, tgt;
    const int* oidx; const float* ow; const float* ctx;
    if (row < E_) {
        widx = wid[row]; tgt = dir[row];
        oidx = noi + row * K_; ow = now + row * K_;
        ctx = xtv + bidx[row] * L_;
    } else {
        int b = row - E_;
        widx = rwid[b]; tgt = 0;
        oidx = roi + b * K_; ow = row_w + b * K_;
        ctx = xtv + b * L_;
    }
    float wsum = 0.f, a = 0.f;
    #pragma unroll
    for (int k = 0; k < K_; k++) {
        int id = oidx[k]; float w = ow[k];
        wsum += w;
        a += w * g_hbuf[id * H_ + tid];
    }
    a /= fmaxf(wsum, 1e-8f);
    float inner = blockReduceSum((tid == 0) ? -a * a : a * a, red);
    float co = a / sqrtf(fmaxf(-inner, 1e-8f));
    float cx = emb[widx * H_ + tid];
    float d0, d1;
    if (tid == 0) {
        float t2s = fmaxf(cx * cx + co * co - 1.f, 1e-8f);
        float c0 = ctx[0];
        float x0 = sqrtf(fmaxf(t2s + c0 * c0 - 1.f, 1e-8f));
        d0 = -x0 * ucls[0];
        d1 = -x0 * ucls[DS_];
    } else {
        d0 = cx * ucls[tid] + co * ucls[255 + tid];
        d1 = cx * ucls[DS_ + tid] + co * ucls[DS_ + 255 + tid];
        if (tid < L_) {
            float cv = ctx[tid];
            d0 += cv * ucls[510 + tid];
            d1 += cv * ucls[DS_ + 510 + tid];
        }
    }
    float sc0 = blockReduceSum(d0, red);
    float sc1 = blockReduceSum(d1, red);
    if (tid == 0) {
        sc0 = 2.f + 2.f * sc0 + ubias[0];
        sc1 = 2.f + 2.f * sc1 + ubias[1];
        float mxv = fmaxf(sc0, sc1);
        float lse = mxv + logf(expf(sc0 - mxv) + expf(sc1 - mxv));
        float ce = lse - ((tgt == 0) ? sc0 : sc1);
        int am = (sc1 > sc0) ? 1 : 0;
        atomicAdd(&g_acc[3], (double)ce);
        atomicAdd(&g_acc[4], (am == tgt) ? 1.0 : 0.0);
    }
}

// ------------------------- finalize ---------------------------------------
__global__ void finalize(float* __restrict__ out) {
    out[0] = (float)(g_acc[0] / (double)B_);
    out[1] = (float)(g_acc[3] / (double)B_);
    out[2] = (float)(g_acc[1] / ((double)B_ + g_acc[2]));
    out[3] = (float)(g_acc[4] / (double)(E_ + B_));
}

// ------------------------- launch ------------------------------------------
extern "C" void kernel_launch(void* const* d_in, const int* in_sizes, int n_in,
                              void* d_out, int out_size) {
    const int*   wid   = (const int*)  d_in[0];
    const int*   nhi   = (const int*)  d_in[1];
    const float* nhw   = (const float*)d_in[2];
    const int*   noi   = (const int*)  d_in[3];
    const float* now_  = (const float*)d_in[4];
    const int*   bidx  = (const int*)  d_in[5];
    const int*   dir   = (const int*)  d_in[6];
    const int*   ptg   = (const int*)  d_in[7];
    const int*   rwid  = (const int*)  d_in[8];
    const int*   roi   = (const int*)  d_in[9];
    const float* row_w = (const float*)d_in[10];
    const float* xtv   = (const float*)d_in[11];
    const float* emb   = (const float*)d_in[12];
    const float* W0    = (const float*)d_in[13];
    const float* b0    = (const float*)d_in[14];
    const float* s0    = (const float*)d_in[15];
    const float* W1    = (const float*)d_in[16];
    const float* b1    = (const float*)d_in[17];
    const float* s1    = (const float*)d_in[18];
    const float* wcls  = (const float*)d_in[19];
    const float* wbias = (const float*)d_in[20];
    const float* ucls  = (const float*)d_in[21];
    const float* ubias = (const float*)d_in[22];
    float* out = (float*)d_out;

    prep_misc<<<1024, 256>>>(W0, W1, wcls);
    prep_pad<<<1, 256>>>(W0, b0, s0);
    for (int t = 0; t < T_; t++)
        step_kernel<<<64, 256>>>(t, wid, nhi, nhw, emb, b0, s0, b1, s1);
    xbuild<<<NROWS, 384>>>(bidx, xtv);
    scores_kernel<<<NROWS / 16, 256>>>(wbias);
    ce_kernel<<<NROWS, 256>>>(dir, ptg, rwid);
    stop_kernel<<<NROWS, 256>>>(wid, noi, now_, bidx, dir, rwid, roi, row_w,
                                xtv, emb, ucls, ubias);
    finalize<<<1, 1>>>(out);
}

// round 5
// speedup vs baseline: 2.1282x; 2.1282x over previous
#include <cuda_runtime.h>
#include <math.h>

#define T_ 64
#define M_ 256
#define K_ 6
#define B_ 256
#define H_ 256
#define L_ 128
#define V_ 780
#define E_ 16384
#define DC_ 383          // wcls cols = H+L-1
#define DS_ 638          // ucls cols = 2H+L-2
#define NROWS (E_ + B_)  // msg rows + root rows
#define NB_ 64           // scan blocks (must all be resident)

// ------------------------- device scratch --------------------------------
__device__ float  g_hbuf [(E_ + 1) * H_];
__device__ float  g_h1buf[(E_ + 1) * H_];
__device__ float  g_W1T  [512 * H_];
__device__ float  g_W0T  [H_ * H_];
__device__ float  g_Gt   [384 * V_];
__device__ float  g_X    [NROWS * 384];
__device__ double g_acc[6];
__device__ volatile int g_bar[T_];

// ------------------------- helpers ---------------------------------------
__device__ __forceinline__ float blockReduceSum(float v, float* sh) {
    __syncthreads();
    #pragma unroll
    for (int o = 16; o > 0; o >>= 1) v += __shfl_down_sync(0xffffffffu, v, o);
    int tid = threadIdx.x;
    if ((tid & 31) == 0) sh[tid >> 5] = v;
    __syncthreads();
    if (tid < 32) {
        int nw = (blockDim.x + 31) >> 5;
        v = (tid < nw) ? sh[tid] : 0.f;
        #pragma unroll
        for (int o = 16; o > 0; o >>= 1) v += __shfl_down_sync(0xffffffffu, v, o);
        if (tid == 0) sh[0] = v;
    }
    __syncthreads();
    return sh[0];
}

// ------------------------- prep -------------------------------------------
__global__ void prep_misc(const float* __restrict__ W0,
                          const float* __restrict__ W1,
                          const float* __restrict__ wcls) {
    if (blockIdx.x == 0 && threadIdx.x < T_) g_bar[threadIdx.x] = 0;
    const int n1 = 512 * H_;
    const int n2 = H_ * H_;
    const int n3 = 384 * V_;
    for (int idx = blockIdx.x * blockDim.x + threadIdx.x;
         idx < n1 + n2 + n3; idx += gridDim.x * blockDim.x) {
        if (idx < n1) {
            int i = idx >> 8, j = idx & 255;
            g_W1T[idx] = (i < 511) ? W1[j * 511 + i] : 0.f;
        } else if (idx < n1 + n2) {
            int k = idx - n1;
            int i = k >> 8, j = k & 255;
            g_W0T[k] = W0[j * H_ + i];
        } else {
            int k = idx - n1 - n2;
            int i = k / V_, v = k % V_;
            float g;
            if (i == 0)       g = -wcls[v * DC_];
            else if (i < DC_) g = wcls[v * DC_ + i];
            else              g = 0.f;
            g_Gt[k] = g;
        }
    }
}

__global__ void prep_pad(const float* __restrict__ W0,
                         const float* __restrict__ b0,
                         const float* __restrict__ s0p) {
    __shared__ float red[32];
    __shared__ float ybc;
    int tid = threadIdx.x;
    if (tid < 6) g_acc[tid] = 0.0;
    g_hbuf[E_ * H_ + tid] = (tid == 0) ? 1.f : 0.f;
    float y = W0[tid * H_] + b0[tid];
    if (tid == 0) ybc = y;
    float ss = blockReduceSum((tid == 0) ? 0.f : y * y, red);
    float time = expf(s0p[0]) / (1.f + expf(-ybc)) + 1.1f;
    float sc = sqrtf((time * time - 1.f) / fmaxf(ss, 1e-8f));
    g_h1buf[E_ * H_ + tid] = (tid == 0) ? time : y * sc;
}

// ------------------------- persistent scan kernel -------------------------
// 64 blocks x 512 threads. Each block: 4 rows/step. Threads: (col = tid&255,
// half = tid>>8). GEMM K-dim split across halves. Grid barrier per step.
__global__ void __launch_bounds__(512, 1) scan_kernel(
    const int*   __restrict__ wid,
    const int*   __restrict__ nhi,
    const float* __restrict__ nhw,
    const float* __restrict__ emb,
    const float* __restrict__ b0,
    const float* __restrict__ s0p,
    const float* __restrict__ b1,
    const float* __restrict__ s1p) {
    __shared__ float svec[4][512];
    __shared__ float shv [4][256];
    __shared__ float part[4][512];
    __shared__ float redsh[4][16];
    __shared__ float ybc[4];

    int tid  = threadIdx.x;
    int col  = tid & 255;
    int half = tid >> 8;
    int warp = tid >> 5;
    int lane = tid & 31;
    int bx   = blockIdx.x;
    float e_s0 = expf(s0p[0]);
    float e_s1 = expf(s1p[0]);
    float bias1 = b1[col];
    float bias0 = b0[col];

    for (int t = 0; t < T_; t++) {
        int ebase = t * M_ + bx * 4;

        // ---- phase 1: gathered midpoint on h1buf + concat build ----------
        #pragma unroll
        for (int rr = 0; rr < 2; rr++) {
            int r = half * 2 + rr;
            int e = ebase + r;
            float wsum = 0.f, a = 0.f;
            #pragma unroll
            for (int k = 0; k < K_; k++) {
                int   id = nhi[e * K_ + k];
                float w  = nhw[e * K_ + k];
                wsum += w;
                a += w * g_h1buf[id * H_ + col];
            }
            a /= fmaxf(wsum, 1e-8f);
            float v = (col == 0) ? a * a : -a * a;   // time^2 - |spatial|^2
            #pragma unroll
            for (int o = 16; o > 0; o >>= 1) v += __shfl_down_sync(0xffffffffu, v, o);
            if (lane == 0) redsh[r][warp & 7] = v;
            __syncthreads();
            float inn = 0.f;
            #pragma unroll
            for (int w8 = 0; w8 < 8; w8++) inn += redsh[r][w8];
            float h1m = a / sqrtf(fmaxf(inn, 1e-8f));
            float cx = emb[wid[e] * H_ + col];
            if (col == 0) {
                svec[r][0]   = sqrtf(fmaxf(cx * cx + h1m * h1m - 1.0f, 1e-8f));
                svec[r][511] = 0.f;
            } else {
                svec[r][col]       = cx;
                svec[r][255 + col] = h1m;
            }
        }
        __syncthreads();

        // ---- phase 2: Y = svec @ W1T  (K=512 split across halves) -------
        float a0 = 0.f, a1 = 0.f, a2 = 0.f, a3 = 0.f;
        {
            const float*  wp  = g_W1T + (half * 256) * H_ + col;
            const float4* s0v = (const float4*)&svec[0][half * 256];
            const float4* s1v = (const float4*)&svec[1][half * 256];
            const float4* s2v = (const float4*)&svec[2][half * 256];
            const float4* s3v = (const float4*)&svec[3][half * 256];
            #pragma unroll 4
            for (int i4 = 0; i4 < 64; i4++) {
                int base = (i4 * 4) * H_;
                float w0 = wp[base], w1 = wp[base + H_];
                float w2 = wp[base + 2 * H_], w3 = wp[base + 3 * H_];
                float4 x0 = s0v[i4], x1 = s1v[i4], x2 = s2v[i4], x3 = s3v[i4];
                a0 += w0 * x0.x + w1 * x0.y + w2 * x0.z + w3 * x0.w;
                a1 += w0 * x1.x + w1 * x1.y + w2 * x1.z + w3 * x1.w;
                a2 += w0 * x2.x + w1 * x2.y + w2 * x2.z + w3 * x2.w;
                a3 += w0 * x3.x + w1 * x3.y + w2 * x3.z + w3 * x3.w;
            }
        }
        part[0][tid] = a0; part[1][tid] = a1; part[2][tid] = a2; part[3][tid] = a3;
        __syncthreads();

        float y[4];
        if (half == 0) {
            #pragma unroll
            for (int r = 0; r < 4; r++) {
                y[r] = part[r][col] + part[r][256 + col] + bias1;
                float v = (col == 0) ? 0.f : y[r] * y[r];
                #pragma unroll
                for (int o = 16; o > 0; o >>= 1) v += __shfl_down_sync(0xffffffffu, v, o);
                if (lane == 0) redsh[r][warp] = v;
                if (col == 0) ybc[r] = y[r];
            }
        }
        __syncthreads();
        if (half == 0) {
            #pragma unroll
            for (int r = 0; r < 4; r++) {
                float ss = 0.f;
                #pragma unroll
                for (int w8 = 0; w8 < 8; w8++) ss += redsh[r][w8];
                float time = e_s1 / (1.f + expf(-ybc[r])) + 1.1f;
                float sc = sqrtf((time * time - 1.f) / fmaxf(ss, 1e-8f));
                float outv = (col == 0) ? time : y[r] * sc;
                g_hbuf[(ebase + r) * H_ + col] = outv;
                shv[r][col] = outv;
            }
        }
        __syncthreads();

        // ---- phase 3: h1 = new_h @ W0T (K=256 split across halves) ------
        float c0 = 0.f, c1 = 0.f, c2 = 0.f, c3 = 0.f;
        {
            const float*  wp  = g_W0T + (half * 128) * H_ + col;
            const float4* s0v = (const float4*)&shv[0][half * 128];
            const float4* s1v = (const float4*)&shv[1][half * 128];
            const float4* s2v = (const float4*)&shv[2][half * 128];
            const float4* s3v = (const float4*)&shv[3][half * 128];
            #pragma unroll 4
            for (int i4 = 0; i4 < 32; i4++) {
                int base = (i4 * 4) * H_;
                float w0 = wp[base], w1 = wp[base + H_];
                float w2 = wp[base + 2 * H_], w3 = wp[base + 3 * H_];
                float4 x0 = s0v[i4], x1 = s1v[i4], x2 = s2v[i4], x3 = s3v[i4];
                c0 += w0 * x0.x + w1 * x0.y + w2 * x0.z + w3 * x0.w;
                c1 += w0 * x1.x + w1 * x1.y + w2 * x1.z + w3 * x1.w;
                c2 += w0 * x2.x + w1 * x2.y + w2 * x2.z + w3 * x2.w;
                c3 += w0 * x3.x + w1 * x3.y + w2 * x3.z + w3 * x3.w;
            }
        }
        part[0][tid] = c0; part[1][tid] = c1; part[2][tid] = c2; part[3][tid] = c3;
        __syncthreads();

        if (half == 0) {
            #pragma unroll
            for (int r = 0; r < 4; r++) {
                y[r] = part[r][col] + part[r][256 + col] + bias0;
                float v = (col == 0) ? 0.f : y[r] * y[r];
                #pragma unroll
                for (int o = 16; o > 0; o >>= 1) v += __shfl_down_sync(0xffffffffu, v, o);
                if (lane == 0) redsh[r][warp] = v;
                if (col == 0) ybc[r] = y[r];
            }
        }
        __syncthreads();
        if (half == 0) {
            #pragma unroll
            for (int r = 0; r < 4; r++) {
                float ss = 0.f;
                #pragma unroll
                for (int w8 = 0; w8 < 8; w8++) ss += redsh[r][w8];
                float time = e_s0 / (1.f + expf(-ybc[r])) + 1.1f;
                float sc = sqrtf((time * time - 1.f) / fmaxf(ss, 1e-8f));
                g_h1buf[(ebase + r) * H_ + col] = (col == 0) ? time : y[r] * sc;
            }
        }

        // ---- grid barrier (release h1buf writes of step t) ---------------
        __threadfence();
        __syncthreads();
        if (tid == 0) {
            atomicAdd((int*)&g_bar[t], 1);
            while (g_bar[t] < NB_) __nanosleep(64);
        }
        __syncthreads();
    }
}

// ------------------------- build X rows for centroid GEMM ----------------
__global__ void xbuild(const int* __restrict__ bidx, const float* __restrict__ xtv) {
    int row = blockIdx.x, tid = threadIdx.x;  // 384 threads
    float v = 0.f;
    if (row < E_) {
        const float* ctx = xtv + bidx[row] * L_;
        if (tid == 0) {
            float n0 = g_hbuf[row * H_];
            float c0 = ctx[0];
            v = sqrtf(fmaxf(n0 * n0 + c0 * c0 - 1.f, 1e-8f));
        } else if (tid < H_) v = g_hbuf[row * H_ + tid];
        else if (tid < DC_)  v = ctx[tid - 255];
    } else {
        const float* ctx = xtv + (row - E_) * L_;
        if (tid == 0) v = sqrtf(fmaxf(ctx[0] * ctx[0], 1e-8f));
        else if (tid >= H_ && tid < DC_) v = ctx[tid - 255];
    }
    g_X[row * 384 + tid] = v;
}

// -------------- fused centroid scores GEMM + softmax CE + argmax ----------
// 16 rows/block, dynamic smem: xs[16][384] + scr[16][788]
__global__ void __launch_bounds__(256) scores_ce_kernel(
    const float* __restrict__ wbias,
    const int*   __restrict__ dir,
    const int*   __restrict__ ptg,
    const int*   __restrict__ rwid) {
    extern __shared__ float dsm[];
    float* xs  = dsm;                // [16][384]
    float* scr = dsm + 16 * 384;     // [16][788]
    int rb = blockIdx.x * 16, tid = threadIdx.x;
    for (int idx = tid; idx < 16 * 384; idx += 256) xs[idx] = g_X[rb * 384 + idx];
    __syncthreads();

    for (int cc = 0; cc < 4; cc++) {
        int colv = cc * 256 + tid;
        if (colv < V_) {
            float acc[16];
            #pragma unroll
            for (int r = 0; r < 16; r++) acc[r] = 0.f;
            for (int i = 0; i < 384; i += 4) {
                float g0 = g_Gt[(i + 0) * V_ + colv];
                float g1 = g_Gt[(i + 1) * V_ + colv];
                float g2 = g_Gt[(i + 2) * V_ + colv];
                float g3 = g_Gt[(i + 3) * V_ + colv];
                #pragma unroll
                for (int r = 0; r < 16; r++) {
                    float4 xv = *(const float4*)&xs[r * 384 + i];
                    acc[r] += g0 * xv.x + g1 * xv.y + g2 * xv.z + g3 * xv.w;
                }
            }
            float bb = wbias[colv];
            #pragma unroll
            for (int r = 0; r < 16; r++)
                scr[r * 788 + colv] = 2.f + 2.f * acc[r] + bb;
        }
    }
    __syncthreads();

    // CE + argmax: warp w handles rows w*2, w*2+1
    int w = tid >> 5, lane = tid & 31;
    #pragma unroll
    for (int rr = 0; rr < 2; rr++) {
        int r = w * 2 + rr;
        int row = rb + r;
        const float* s = scr + r * 788;
        float mx = -1e30f; int mi = 0x7fffffff;
        for (int j = lane; j < V_; j += 32) {
            float v = s[j];
            if (v > mx) { mx = v; mi = j; }
        }
        #pragma unroll
        for (int o = 16; o > 0; o >>= 1) {
            float om = __shfl_down_sync(0xffffffffu, mx, o);
            int   oi = __shfl_down_sync(0xffffffffu, mi, o);
            if (om > mx || (om == mx && oi < mi)) { mx = om; mi = oi; }
        }
        mx = __shfl_sync(0xffffffffu, mx, 0);
        mi = __shfl_sync(0xffffffffu, mi, 0);
        float p = 0.f;
        for (int j = lane; j < V_; j += 32) p += __expf(s[j] - mx);
        #pragma unroll
        for (int o = 16; o > 0; o >>= 1) p += __shfl_down_sync(0xffffffffu, p, o);
        if (lane == 0) {
            float lse = mx + logf(p);
            if (row < E_) {
                float pm = (float)dir[row];
                int tgt = ptg[row];
                float ce = lse - s[tgt];
                atomicAdd(&g_acc[0], (double)(pm * ce));
                atomicAdd(&g_acc[1], (double)(pm * ((mi == tgt) ? 1.f : 0.f)));
                atomicAdd(&g_acc[2], (double)pm);
            } else {
                int tgt = rwid[row - E_];
                float ce = lse - s[tgt];
                atomicAdd(&g_acc[0], (double)ce);
                atomicAdd(&g_acc[1], (mi == tgt) ? 1.0 : 0.0);
            }
        }
    }
}

// ------------------------- stop head --------------------------------------
__global__ void stop_kernel(const int*   __restrict__ wid,
                            const int*   __restrict__ noi,
                            const float* __restrict__ now,
                            const int*   __restrict__ bidx,
                            const int*   __restrict__ dir,
                            const int*   __restrict__ rwid,
                            const int*   __restrict__ roi,
                            const float* __restrict__ row_w,
                            const float* __restrict__ xtv,
                            const float* __restrict__ emb,
                            const float* __restrict__ ucls,
                            const float* __restrict__ ubias) {
    int row = blockIdx.x, tid = threadIdx.x;
    __shared__ float red[32];
    int widx, tgt;
    const int* oidx; const float* ow; const float* ctx;
    if (row < E_) {
        widx = wid[row]; tgt = dir[row];
        oidx = noi + row * K_; ow = now + row * K_;
        ctx = xtv + bidx[row] * L_;
    } else {
        int b = row - E_;
        widx = rwid[b]; tgt = 0;
        oidx = roi + b * K_; ow = row_w + b * K_;
        ctx = xtv + b * L_;
    }
    float wsum = 0.f, a = 0.f;
    #pragma unroll
    for (int k = 0; k < K_; k++) {
        int id = oidx[k]; float w = ow[k];
        wsum += w;
        a += w * g_hbuf[id * H_ + tid];
    }
    a /= fmaxf(wsum, 1e-8f);
    float inner = blockReduceSum((tid == 0) ? -a * a : a * a, red);
    float co = a / sqrtf(fmaxf(-inner, 1e-8f));
    float cx = emb[widx * H_ + tid];
    float d0, d1;
    if (tid == 0) {
        float t2s = fmaxf(cx * cx + co * co - 1.f, 1e-8f);
        float c0 = ctx[0];
        float x0 = sqrtf(fmaxf(t2s + c0 * c0 - 1.f, 1e-8f));
        d0 = -x0 * ucls[0];
        d1 = -x0 * ucls[DS_];
    } else {
        d0 = cx * ucls[tid] + co * ucls[255 + tid];
        d1 = cx * ucls[DS_ + tid] + co * ucls[DS_ + 255 + tid];
        if (tid < L_) {
            float cv = ctx[tid];
            d0 += cv * ucls[510 + tid];
            d1 += cv * ucls[DS_ + 510 + tid];
        }
    }
    float sc0 = blockReduceSum(d0, red);
    float sc1 = blockReduceSum(d1, red);
    if (tid == 0) {
        sc0 = 2.f + 2.f * sc0 + ubias[0];
        sc1 = 2.f + 2.f * sc1 + ubias[1];
        float mxv = fmaxf(sc0, sc1);
        float lse = mxv + logf(expf(sc0 - mxv) + expf(sc1 - mxv));
        float ce = lse - ((tgt == 0) ? sc0 : sc1);
        int am = (sc1 > sc0) ? 1 : 0;
        atomicAdd(&g_acc[3], (double)ce);
        atomicAdd(&g_acc[4], (am == tgt) ? 1.0 : 0.0);
    }
}

// ------------------------- finalize ---------------------------------------
__global__ void finalize(float* __restrict__ out) {
    out[0] = (float)(g_acc[0] / (double)B_);
    out[1] = (float)(g_acc[3] / (double)B_);
    out[2] = (float)(g_acc[1] / ((double)B_ + g_acc[2]));
    out[3] = (float)(g_acc[4] / (double)(E_ + B_));
}

// ------------------------- launch ------------------------------------------
extern "C" void kernel_launch(void* const* d_in, const int* in_sizes, int n_in,
                              void* d_out, int out_size) {
    const int*   wid   = (const int*)  d_in[0];
    const int*   nhi   = (const int*)  d_in[1];
    const float* nhw   = (const float*)d_in[2];
    const int*   noi   = (const int*)  d_in[3];
    const float* now_  = (const float*)d_in[4];
    const int*   bidx  = (const int*)  d_in[5];
    const int*   dir   = (const int*)  d_in[6];
    const int*   ptg   = (const int*)  d_in[7];
    const int*   rwid  = (const int*)  d_in[8];
    const int*   roi   = (const int*)  d_in[9];
    const float* row_w = (const float*)d_in[10];
    const float* xtv   = (const float*)d_in[11];
    const float* emb   = (const float*)d_in[12];
    const float* W0    = (const float*)d_in[13];
    const float* b0    = (const float*)d_in[14];
    const float* s0    = (const float*)d_in[15];
    const float* W1    = (const float*)d_in[16];
    const float* b1    = (const float*)d_in[17];
    const float* s1    = (const float*)d_in[18];
    const float* wcls  = (const float*)d_in[19];
    const float* wbias = (const float*)d_in[20];
    const float* ucls  = (const float*)d_in[21];
    const float* ubias = (const float*)d_in[22];
    float* out = (float*)d_out;

    const int smem_ce = (16 * 384 + 16 * 788) * sizeof(float);  // ~75 KB
    cudaFuncSetAttribute(scores_ce_kernel,
                         cudaFuncAttributeMaxDynamicSharedMemorySize, smem_ce);

    prep_misc<<<1024, 256>>>(W0, W1, wcls);
    prep_pad<<<1, 256>>>(W0, b0, s0);
    scan_kernel<<<NB_, 512>>>(wid, nhi, nhw, emb, b0, s0, b1, s1);
    xbuild<<<NROWS, 384>>>(bidx, xtv);
    scores_ce_kernel<<<NROWS / 16, 256, smem_ce>>>(wbias, dir, ptg, rwid);
    stop_kernel<<<NROWS, 256>>>(wid, noi, now_, bidx, dir, rwid, roi, row_w,
                                xtv, emb, ucls, ubias);
    finalize<<<1, 1>>>(out);
}